// round 14
// baseline (speedup 1.0000x reference)
#include <cuda_runtime.h>
#include <cuda_fp16.h>
#include <math.h>
#include <stdint.h>

#define N_TOK   16384
#define DDIM    2048
#define NEXP    64
#define TM      32
#define NKS     (DDIM / 16)     // 128 k-steps of 16
#define NCH     (DDIM / 64)     // 32 chunks of 64 k (4 k-steps)
#define TOPK    8
#define THREADS 256
#define LPAD    66

#define WSC       1024.0f           // 2^10 on W only
#define SCALE_INV 9.765625e-04f     // 2^-10

// B fragments (pi-permuted k), hi/lo interleaved: [ks][nb*32+lane]={hi0,hi1,lo0,lo1}
__device__ __align__(128) uint4 g_Bfrag[NKS * 256];

static __device__ __forceinline__ uint32_t h2u(__half2 h) {
    return reinterpret_cast<uint32_t&>(h);
}
static __device__ __forceinline__ uint32_t s2u(const void* p) {
    uint32_t a;
    asm("{ .reg .u64 t; cvta.to.shared.u64 t, %1; cvt.u32.u64 %0, t; }" : "=r"(a) : "l"(p));
    return a;
}

static __device__ __forceinline__ void hmma(float* c, const uint32_t* a,
                                            uint32_t b0, uint32_t b1) {
    asm("mma.sync.aligned.m16n8k16.row.col.f32.f16.f16.f32 "
        "{%0,%1,%2,%3}, {%4,%5,%6,%7}, {%8,%9}, {%0,%1,%2,%3};"
        : "+f"(c[0]), "+f"(c[1]), "+f"(c[2]), "+f"(c[3])
        : "r"(a[0]), "r"(a[1]), "r"(a[2]), "r"(a[3]), "r"(b0), "r"(b1));
}

// split 2 floats -> hi half2 + lo residual half2
static __device__ __forceinline__ void split2(float v0, float v1,
                                              uint32_t& hi, uint32_t& lo) {
    __half2 h = __floats2half2_rn(v0, v1);
    float2 hf = __half22float2(h);
    __half2 r = __floats2half2_rn(v0 - hf.x, v1 - hf.y);
    hi = h2u(h); lo = h2u(r);
}

// r0 = row g float4, r1 = row g+8 float4 (one pi-permuted k-step)
static __device__ __forceinline__ void cvtf4(float4 r0, float4 r1,
                                             uint32_t* ahi, uint32_t* alo) {
    split2(r0.x, r0.y, ahi[0], alo[0]);
    split2(r1.x, r1.y, ahi[1], alo[1]);
    split2(r0.z, r0.w, ahi[2], alo[2]);
    split2(r1.z, r1.w, ahi[3], alo[3]);
}

// ---- prep: W -> pi-permuted fragments (lane t=l&3 slots hold cols 4t..4t+3) ----
__global__ void __launch_bounds__(256) wprep_kernel(const float* __restrict__ W) {
    int idx = blockIdx.x * 256 + threadIdx.x;        // 32768 = (ks, nb, lane)
    int l = idx & 31, nb = (idx >> 5) & 7, ks = idx >> 8;
    int n = nb * 8 + (l >> 2);
    int k = ks * 16 + (l & 3) * 4;
    float4 w = *(const float4*)(W + (size_t)n * DDIM + k);
    float a0 = w.x * WSC, a1 = w.y * WSC, a2 = w.z * WSC, a3 = w.w * WSC;
    uint32_t h0, l0, h1, l1;
    split2(a0, a1, h0, l0);
    split2(a2, a3, h1, l1);
    g_Bfrag[ks * 256 + nb * 32 + l] = make_uint4(h0, h1, l0, l1);
}

static __device__ __forceinline__ void cp16s(uint32_t dst, const void* gsrc) {
    asm volatile("cp.async.ca.shared.global [%0], [%1], 16;" :: "r"(dst), "l"(gsrc));
}

// ---- fused router: TM=32, (rg x 4 kh-pairs), pair-staged B, 3 CTAs/SM ----
__global__ void __launch_bounds__(THREADS, 3)
router_kernel(const float* __restrict__ x, const float* __restrict__ bias,
              float* __restrict__ out) {
    __shared__ __align__(16) uint4 bbuf[4][2][256];  // per-kh-pair 2-stage (32 KB)
    __shared__ float logits[TM][LPAD];

    const int tid = threadIdx.x;
    const int wid = tid >> 5, l = tid & 31;
    const int rg  = wid & 1;           // row group: tokens rg? no - rows via g below
    const int kh  = wid >> 1;          // k quarter: k-step c*4+kh of each chunk
    const int g = l >> 2, kq = (l & 3) * 4;
    const int t0 = blockIdx.x * TM;

    const float* xr0 = x + (size_t)(t0 + g) * DDIM + kh * 16 + kq;   // rows g, g+8
    const float* xr1 = xr0 + 8 * DDIM;
    const float* xr2 = xr0 + 16 * DDIM;                              // rows g+16, g+24
    const float* xr3 = xr0 + 24 * DDIM;

    // rg selects which 16-row half this warp computes
    const float* ar0 = rg ? xr2 : xr0;
    const float* ar1 = rg ? xr3 : xr1;

    const uint32_t sb0 = s2u(&bbuf[kh][0][0]);
    const uint32_t sb1 = s2u(&bbuf[kh][1][0]);

    float acc[8][4];
    #pragma unroll
    for (int nb = 0; nb < 8; nb++)
        #pragma unroll
        for (int c = 0; c < 4; c++) acc[nb][c] = 0.0f;

    // prologue: producer (rg==0) stages chunk 0's k-step into stage 0
    if (rg == 0) {
        const uint4* src = g_Bfrag + (size_t)kh * 256 + l;
        #pragma unroll
        for (int nb = 0; nb < 8; nb++)
            cp16s(sb0 + (nb * 32 + l) * 16, src + nb * 32);
        asm volatile("cp.async.commit_group;");
    }

    // A raw for chunk 0
    float4 raw0 = *(const float4*)(ar0);
    float4 raw1 = *(const float4*)(ar1);

    for (int c = 0; c < NCH; c++) {
        if (rg == 0) {
            if (c + 1 < NCH) {
                const uint4* src = g_Bfrag + ((size_t)(c + 1) * 4 + kh) * 256 + l;
                uint32_t dst = ((c + 1) & 1) ? sb1 : sb0;
                #pragma unroll
                for (int nb = 0; nb < 8; nb++)
                    cp16s(dst + (nb * 32 + l) * 16, src + nb * 32);
                asm volatile("cp.async.commit_group;");
                asm volatile("cp.async.wait_group 1;");   // chunk c's group done
            } else {
                asm volatile("cp.async.wait_group 0;");
            }
        }
        asm volatile("bar.sync %0, 64;" :: "r"(kh + 1) : "memory");

        // convert current A + prefetch next chunk's A
        uint32_t ahi[4], alo[4];
        cvtf4(raw0, raw1, ahi, alo);
        const int kn = ((c + 1 < NCH) ? (c + 1) : c) * 64;
        raw0 = *(const float4*)(ar0 + kn);
        raw1 = *(const float4*)(ar1 + kn);

        const uint4* bp = (c & 1) ? &bbuf[kh][1][0] : &bbuf[kh][0][0];
        #pragma unroll
        for (int nb = 0; nb < 8; nb++) {
            uint4 b = bp[nb * 32 + l];           // LDS.128, conflict-free
            hmma(acc[nb], ahi, b.x, b.y);
            hmma(acc[nb], ahi, b.z, b.w);
            hmma(acc[nb], alo, b.x, b.y);
        }
    }

    // ---- combine 8 warp partials (2 rg x 4 kh) in smem logits, then top-8 ----
    const int r0 = rg * 16 + g;
    const int kp = (l & 3) * 2;          // D-frag columns (unpermuted)
    __syncthreads();
    if (kh == 0) {
        #pragma unroll
        for (int nb = 0; nb < 8; nb++) {
            int c0 = nb * 8 + kp;
            *(float2*)&logits[r0][c0]     = make_float2(acc[nb][0], acc[nb][1]);
            *(float2*)&logits[r0 + 8][c0] = make_float2(acc[nb][2], acc[nb][3]);
        }
    }
    #pragma unroll
    for (int q = 1; q < 4; q++) {
        __syncthreads();
        if (kh == q) {
            #pragma unroll
            for (int nb = 0; nb < 8; nb++) {
                int c0 = nb * 8 + kp;
                float2 p0 = *(float2*)&logits[r0][c0];
                float2 p1 = *(float2*)&logits[r0 + 8][c0];
                *(float2*)&logits[r0][c0] =
                    make_float2(p0.x + acc[nb][0], p0.y + acc[nb][1]);
                *(float2*)&logits[r0 + 8][c0] =
                    make_float2(p1.x + acc[nb][2], p1.y + acc[nb][3]);
            }
        }
    }
    __syncthreads();

    if (tid < TM) {
        const float* p = &logits[tid][0];
        float val[TOPK]; int idx[TOPK];
        #pragma unroll
        for (int r = 0; r < TOPK; r++) { val[r] = -INFINITY; idx[r] = 0; }

        for (int e = 0; e < NEXP; e++) {
            float z = p[e] * SCALE_INV + __ldg(&bias[e]);
            float sc = 1.0f / (1.0f + __expf(-z));   // monotone: order preserved
            if (sc > val[TOPK - 1]) {                // strict >: first index wins ties
                int pos = TOPK - 1;
                while (pos > 0 && sc > val[pos - 1]) {
                    val[pos] = val[pos - 1]; idx[pos] = idx[pos - 1]; pos--;
                }
                val[pos] = sc; idx[pos] = e;
            }
        }

        int t = t0 + tid;
        #pragma unroll
        for (int r = 0; r < TOPK; r++) {
            out[(size_t)t * TOPK + r] = val[r];
            out[(size_t)N_TOK * TOPK + (size_t)t * TOPK + r] = (float)idx[r];
        }
    }
}

extern "C" void kernel_launch(void* const* d_in, const int* in_sizes, int n_in,
                              void* d_out, int out_size) {
    const float* x = (const float*)d_in[0];
    const float* W = (const float*)d_in[1];
    const float* b = (const float*)d_in[2];
    float* out = (float*)d_out;

    wprep_kernel<<<NKS * 256 / 256, 256>>>(W);
    router_kernel<<<N_TOK / TM, THREADS>>>(x, b, out);
}

// round 15
// speedup vs baseline: 1.4937x; 1.4937x over previous
#include <cuda_runtime.h>
#include <cuda_fp16.h>
#include <math.h>
#include <stdint.h>

#define N_TOK   16384
#define DDIM    2048
#define NEXP    64
#define TM      64
#define NKS     (DDIM / 16)     // 128 k-steps of 16
#define NIT     (DDIM / 32)     // 64 iterations of 2 k-steps
#define TOPK    8
#define THREADS 256
#define LPAD    66

#define WSC       1024.0f           // 2^10 on W only
#define SCALE_INV 9.765625e-04f     // 2^-10

// B fragments (pi-permuted k), hi/lo interleaved: [ks][nb*32+lane]={hi0,hi1,lo0,lo1}
__device__ __align__(128) uint4 g_Bfrag[NKS * 256];

static __device__ __forceinline__ uint32_t h2u(__half2 h) {
    return reinterpret_cast<uint32_t&>(h);
}

static __device__ __forceinline__ void hmma(float* c, const uint32_t* a,
                                            uint32_t b0, uint32_t b1) {
    asm("mma.sync.aligned.m16n8k16.row.col.f32.f16.f16.f32 "
        "{%0,%1,%2,%3}, {%4,%5,%6,%7}, {%8,%9}, {%0,%1,%2,%3};"
        : "+f"(c[0]), "+f"(c[1]), "+f"(c[2]), "+f"(c[3])
        : "r"(a[0]), "r"(a[1]), "r"(a[2]), "r"(a[3]), "r"(b0), "r"(b1));
}

// split 2 floats -> hi half2 + lo residual half2
static __device__ __forceinline__ void split2(float v0, float v1,
                                              uint32_t& hi, uint32_t& lo) {
    __half2 h = __floats2half2_rn(v0, v1);
    float2 hf = __half22float2(h);
    __half2 r = __floats2half2_rn(v0 - hf.x, v1 - hf.y);
    hi = h2u(h); lo = h2u(r);
}

// r0 = row g float4, r1 = row g+8 float4 (one pi-permuted k-step)
static __device__ __forceinline__ void cvtf4(float4 r0, float4 r1,
                                             uint32_t* ahi, uint32_t* alo) {
    split2(r0.x, r0.y, ahi[0], alo[0]);
    split2(r1.x, r1.y, ahi[1], alo[1]);
    split2(r0.z, r0.w, ahi[2], alo[2]);
    split2(r1.z, r1.w, ahi[3], alo[3]);
}

// ---- prep: W -> pi-permuted fragments (lane t=l&3 slots hold cols 4t..4t+3) ----
__global__ void __launch_bounds__(256) wprep_kernel(const float* __restrict__ W) {
    int idx = blockIdx.x * 256 + threadIdx.x;        // 32768 = (ks, nb, lane)
    int l = idx & 31, nb = (idx >> 5) & 7, ks = idx >> 8;
    int n = nb * 8 + (l >> 2);
    int k = ks * 16 + (l & 3) * 4;
    float4 w = *(const float4*)(W + (size_t)n * DDIM + k);
    float a0 = w.x * WSC, a1 = w.y * WSC, a2 = w.z * WSC, a3 = w.w * WSC;
    uint32_t h0, l0, h1, l1;
    split2(a0, a1, h0, l0);
    split2(a2, a3, h1, l1);
    g_Bfrag[ks * 256 + nb * 32 + l] = make_uint4(h0, h1, l0, l1);
}

static __device__ __forceinline__ void ldB4(uint4 b[4], const uint4* gb, int ks) {
    const uint4* p = gb + ks * 256;
    #pragma unroll
    for (int nb = 0; nb < 4; nb++) b[nb] = __ldg(p + nb * 32);
}

static __device__ __forceinline__ void mma_step4(float acc[4][4],
                                                 const uint32_t* ahi, const uint32_t* alo,
                                                 const uint4 b[4]) {
    #pragma unroll
    for (int nb = 0; nb < 4; nb++) {
        hmma(acc[nb], ahi, b[nb].x, b[nb].y);
        hmma(acc[nb], ahi, b[nb].z, b[nb].w);
        hmma(acc[nb], alo, b[nb].x, b[nb].y);
    }
}

// ---- fused router: TM=64, n-split warps, 3 CTAs/SM, zero mainloop sync ----
__global__ void __launch_bounds__(THREADS, 3)
router_kernel(const float* __restrict__ x, const float* __restrict__ bias,
              float* __restrict__ out) {
    __shared__ float logits[TM][LPAD];

    const int tid = threadIdx.x;
    const int wid = tid >> 5, l = tid & 31;
    const int rg  = wid & 3;           // row group: rows rg*16 .. rg*16+15
    const int ns  = wid >> 2;          // expert half: nb_global = ns*4 + nb
    const int g = l >> 2, kq = (l & 3) * 4;
    const int t0 = blockIdx.x * TM;

    const float* xr0 = x + (size_t)(t0 + rg * 16 + g) * DDIM + kq;
    const float* xr1 = xr0 + 8 * DDIM;
    const uint4* gb = g_Bfrag + ns * 128 + l;     // nb offset folded: +nb*32 in ldB4

    float acc[4][4];
    #pragma unroll
    for (int nb = 0; nb < 4; nb++)
        #pragma unroll
        for (int c = 0; c < 4; c++) acc[nb][c] = 0.0f;

    // A raw for iter 0: 2 k-steps x 2 rows
    float4 raw[4];
    #pragma unroll
    for (int s = 0; s < 2; s++) {
        raw[s * 2 + 0] = *(const float4*)(xr0 + s * 16);
        raw[s * 2 + 1] = *(const float4*)(xr1 + s * 16);
    }

    uint4 bc[4], bn[4];
    ldB4(bc, gb, 0);

    for (int it = 0; it < NIT; it++) {
        const int ksA = it * 2;
        const int kn = ((it + 1 < NIT) ? (it + 1) : it) * 32;

        uint32_t ahi0[4], alo0[4], ahi1[4], alo1[4];
        cvtf4(raw[0], raw[1], ahi0, alo0);
        cvtf4(raw[2], raw[3], ahi1, alo1);

        // prefetch A raw for next iter (4 x LDG.128)
        #pragma unroll
        for (int s = 0; s < 2; s++) {
            raw[s * 2 + 0] = *(const float4*)(xr0 + kn + s * 16);
            raw[s * 2 + 1] = *(const float4*)(xr1 + kn + s * 16);
        }

        ldB4(bn, gb, ksA + 1);
        mma_step4(acc, ahi0, alo0, bc);
        ldB4(bc, gb, (it + 1 < NIT) ? ksA + 2 : ksA + 1);
        mma_step4(acc, ahi1, alo1, bn);
    }

    // ---- each warp owns its logits block outright: direct write, no combine ----
    const int r0 = rg * 16 + g;
    const int kp = (l & 3) * 2;          // D-frag columns (unpermuted)
    #pragma unroll
    for (int nb = 0; nb < 4; nb++) {
        int c0 = (ns * 4 + nb) * 8 + kp;
        *(float2*)&logits[r0][c0]     = make_float2(acc[nb][0], acc[nb][1]);
        *(float2*)&logits[r0 + 8][c0] = make_float2(acc[nb][2], acc[nb][3]);
    }
    __syncthreads();

    if (tid < TM) {
        const float* p = &logits[tid][0];
        float val[TOPK]; int idx[TOPK];
        #pragma unroll
        for (int r = 0; r < TOPK; r++) { val[r] = -INFINITY; idx[r] = 0; }

        for (int e = 0; e < NEXP; e++) {
            float z = p[e] * SCALE_INV + __ldg(&bias[e]);
            float sc = 1.0f / (1.0f + __expf(-z));   // monotone: order preserved
            if (sc > val[TOPK - 1]) {                // strict >: first index wins ties
                int pos = TOPK - 1;
                while (pos > 0 && sc > val[pos - 1]) {
                    val[pos] = val[pos - 1]; idx[pos] = idx[pos - 1]; pos--;
                }
                val[pos] = sc; idx[pos] = e;
            }
        }

        int t = t0 + tid;
        #pragma unroll
        for (int r = 0; r < TOPK; r++) {
            out[(size_t)t * TOPK + r] = val[r];
            out[(size_t)N_TOK * TOPK + (size_t)t * TOPK + r] = (float)idx[r];
        }
    }
}

extern "C" void kernel_launch(void* const* d_in, const int* in_sizes, int n_in,
                              void* d_out, int out_size) {
    const float* x = (const float*)d_in[0];
    const float* W = (const float*)d_in[1];
    const float* b = (const float*)d_in[2];
    float* out = (float*)d_out;

    wprep_kernel<<<NKS * 256 / 256, 256>>>(W);
    router_kernel<<<N_TOK / TM, THREADS>>>(x, b, out);
}